// round 13
// baseline (speedup 1.0000x reference)
#include <cuda_runtime.h>
#include <cuda_bf16.h>
#include <cstdint>

// Problem constants
constexpr int B = 4, C = 64, H = 96, W = 96, F = 64, E = 8;
constexpr int WS = 21, PS = 10, KNN = 7, Rr = 10, NOFF = WS * WS; // 441
constexpr int HW = H * W;
constexpr float BIGV = 1e10f;
constexpr int NSLICE = 24;               // BN reduction slices

// ---------------- scratch (device globals; no allocation allowed) ----------
__device__ float g_t1[B * C * HW];            // conv1 raw output
__device__ float g_t2[B * C * HW];            // conv2 raw output
__device__ float g_xe[B * HW * E];            // embedding, [B,H,W,E]
__device__ float g_xt[B * HW * C];            // x transposed, [B,H,W,C]
__device__ float g_hs[NOFF * B * HW];         // horizontal 10-window sums
__device__ float g_D [NOFF * B * HW];         // full 10x10 distances (masked)
__device__ float g_bnscale[2][C];
__device__ float g_bnshift[2][C];
__device__ double g_bnpart[2][C][NSLICE][2];  // partial (sum, sumsq)

// ---------------- conv 3x3 SAME (stages 0/1: 64->64) ------------------------
// block (16,4) = 64 thr: 16x16 tile, each thread 1 col x 4 rows, 8 co.
// Halo slots precomputed, weights padded for LDS.128, double-buffered tile.
template<int STAGE>
__global__ void __launch_bounds__(64) conv3x3_k(const float* __restrict__ xin,
                                                const float* __restrict__ wgt)
{
    constexpr int CIN = 64;
    const float* in = (STAGE == 0) ? xin : g_t1;
    float* outp     = (STAGE == 0) ? g_t1 : g_t2;

    const int tx = threadIdx.x, ty = threadIdx.y;
    const int tid = ty * 16 + tx;
    const int gx0 = blockIdx.x * 16, gy0 = blockIdx.y * 16;
    const int b   = blockIdx.z >> 3;
    const int co0 = (blockIdx.z & 7) * 8;

    __shared__ __align__(16) float wsm[CIN][8][12];  // padded: 2xLDS.128+LDS.32
    __shared__ float tile[2][344];                   // 18x19 + dump slot 343

    for (int i = tid; i < CIN * 8 * 9; i += 64) {
        int cin = i / 72, rem = i % 72, co = rem / 9, k = rem % 9;
        wsm[cin][co][k] = wgt[((co0 + co) * CIN + cin) * 9 + k];
    }

    int  sm_idx[6];
    int  goff[6];
    bool inb[6];
    #pragma unroll
    for (int s = 0; s < 6; s++) {
        int i = tid + s * 64;
        if (i < 324) {
            int r = i / 18, c = i % 18;
            int gy = gy0 + r - 1, gx = gx0 + c - 1;
            bool ok = (gy >= 0) && (gy < H) && (gx >= 0) && (gx < W);
            sm_idx[s] = r * 19 + c;
            goff[s]   = ok ? (gy * W + gx) : 0;
            inb[s]    = ok;
        } else {
            sm_idx[s] = 343; goff[s] = 0; inb[s] = false;
        }
    }

    const float* ipb = in + (size_t)b * CIN * HW;

    float acc[8][4];
    #pragma unroll
    for (int co = 0; co < 8; co++)
        #pragma unroll
        for (int p = 0; p < 4; p++) acc[co][p] = 0.f;

    {
        float sc = 1.f, sh = 0.f;
        if (STAGE == 1) { sc = g_bnscale[0][0]; sh = g_bnshift[0][0]; }
        #pragma unroll
        for (int s = 0; s < 6; s++) {
            float v = 0.f;
            if (inb[s]) {
                v = ipb[goff[s]];
                if (STAGE == 1) v = fmaxf(v * sc + sh, 0.f);
            }
            tile[0][sm_idx[s]] = v;
        }
    }
    __syncthreads();

    for (int cin = 0; cin < CIN; cin++) {
        const int cur = cin & 1;

        if (cin + 1 < CIN) {
            float sc = 1.f, sh = 0.f;
            if (STAGE == 1) { sc = g_bnscale[0][cin + 1]; sh = g_bnshift[0][cin + 1]; }
            const float* ip = ipb + (size_t)(cin + 1) * HW;
            #pragma unroll
            for (int s = 0; s < 6; s++) {
                float v = 0.f;
                if (inb[s]) {
                    v = ip[goff[s]];
                    if (STAGE == 1) v = fmaxf(v * sc + sh, 0.f);
                }
                tile[cur ^ 1][sm_idx[s]] = v;
            }
        }

        const float* tb = tile[cur];
        float tin[6][3];
        #pragma unroll
        for (int rr = 0; rr < 6; rr++)
            #pragma unroll
            for (int cc = 0; cc < 3; cc++)
                tin[rr][cc] = tb[(ty * 4 + rr) * 19 + tx + cc];

        #pragma unroll
        for (int co = 0; co < 8; co++) {
            const float4 w0 = *(const float4*)&wsm[cin][co][0];
            const float4 w1 = *(const float4*)&wsm[cin][co][4];
            const float  w8 = wsm[cin][co][8];
            #pragma unroll
            for (int p = 0; p < 4; p++) {
                float a = acc[co][p];
                a += w0.x * tin[p    ][0];
                a += w0.y * tin[p    ][1];
                a += w0.z * tin[p    ][2];
                a += w0.w * tin[p + 1][0];
                a += w1.x * tin[p + 1][1];
                a += w1.y * tin[p + 1][2];
                a += w1.z * tin[p + 2][0];
                a += w1.w * tin[p + 2][1];
                a += w8   * tin[p + 2][2];
                acc[co][p] = a;
            }
        }
        __syncthreads();
    }

    #pragma unroll
    for (int co = 0; co < 8; co++) {
        #pragma unroll
        for (int p = 0; p < 4; p++) {
            int gy = gy0 + ty * 4 + p, gx = gx0 + tx;
            outp[((size_t)(b * CIN + co0 + co) * H + gy) * W + gx] = acc[co][p];
        }
    }
}

// ---------------- conv3: 64->8 embedding, tile 16x4 (occupancy fix) ---------
__global__ void __launch_bounds__(64) conv3e_k(const float* __restrict__ wgt,
                                               const float* __restrict__ bias)
{
    constexpr int CIN = 64;
    const int tx = threadIdx.x, ty = threadIdx.y;      // (16,4)
    const int tid = ty * 16 + tx;
    const int gx0 = blockIdx.x * 16, gy0 = blockIdx.y * 4;
    const int b   = blockIdx.z;

    __shared__ __align__(16) float wsm[CIN][8][12];
    __shared__ float tile[2][120];                     // 6x19 + dump slot 119

    for (int i = tid; i < CIN * 8 * 9; i += 64) {
        int cin = i / 72, rem = i % 72, co = rem / 9, k = rem % 9;
        wsm[cin][co][k] = wgt[(co * CIN + cin) * 9 + k];
    }

    // halo: 6 rows x 18 cols = 108 slots -> 2 per thread
    int  sm_idx[2];
    int  goff[2];
    bool inb[2];
    #pragma unroll
    for (int s = 0; s < 2; s++) {
        int i = tid + s * 64;
        if (i < 108) {
            int r = i / 18, c = i % 18;
            int gy = gy0 + r - 1, gx = gx0 + c - 1;
            bool ok = (gy >= 0) && (gy < H) && (gx >= 0) && (gx < W);
            sm_idx[s] = r * 19 + c;
            goff[s]   = ok ? (gy * W + gx) : 0;
            inb[s]    = ok;
        } else {
            sm_idx[s] = 119; goff[s] = 0; inb[s] = false;
        }
    }

    const float* ipb = g_t2 + (size_t)b * CIN * HW;

    float acc[8];
    #pragma unroll
    for (int co = 0; co < 8; co++) acc[co] = 0.f;

    {
        float sc = g_bnscale[1][0], sh = g_bnshift[1][0];
        #pragma unroll
        for (int s = 0; s < 2; s++) {
            float v = 0.f;
            if (inb[s]) v = fmaxf(ipb[goff[s]] * sc + sh, 0.f);
            tile[0][sm_idx[s]] = v;
        }
    }
    __syncthreads();

    for (int cin = 0; cin < CIN; cin++) {
        const int cur = cin & 1;
        if (cin + 1 < CIN) {
            float sc = g_bnscale[1][cin + 1], sh = g_bnshift[1][cin + 1];
            const float* ip = ipb + (size_t)(cin + 1) * HW;
            #pragma unroll
            for (int s = 0; s < 2; s++) {
                float v = 0.f;
                if (inb[s]) v = fmaxf(ip[goff[s]] * sc + sh, 0.f);
                tile[cur ^ 1][sm_idx[s]] = v;
            }
        }

        const float* tb = tile[cur];
        float tin[3][3];
        #pragma unroll
        for (int rr = 0; rr < 3; rr++)
            #pragma unroll
            for (int cc = 0; cc < 3; cc++)
                tin[rr][cc] = tb[(ty + rr) * 19 + tx + cc];

        #pragma unroll
        for (int co = 0; co < 8; co++) {
            const float4 w0 = *(const float4*)&wsm[cin][co][0];
            const float4 w1 = *(const float4*)&wsm[cin][co][4];
            const float  w8 = wsm[cin][co][8];
            float a = acc[co];
            a += w0.x * tin[0][0];
            a += w0.y * tin[0][1];
            a += w0.z * tin[0][2];
            a += w0.w * tin[1][0];
            a += w1.x * tin[1][1];
            a += w1.y * tin[1][2];
            a += w1.z * tin[2][0];
            a += w1.w * tin[2][1];
            a += w8   * tin[2][2];
            acc[co] = a;
        }
        __syncthreads();
    }

    const int gy = gy0 + ty, gx = gx0 + tx;
    float4 o0 = make_float4(acc[0] + bias[0], acc[1] + bias[1],
                            acc[2] + bias[2], acc[3] + bias[3]);
    float4 o1 = make_float4(acc[4] + bias[4], acc[5] + bias[5],
                            acc[6] + bias[6], acc[7] + bias[7]);
    float* dst = g_xe + ((size_t)(b * H + gy) * W + gx) * E;
    *(float4*)dst       = o0;
    *(float4*)(dst + 4) = o1;
}

// ---------------- BN statistics: two-stage deterministic --------------------
template<int SLOT>
__global__ void bn_partial_k()
{
    const float* t = (SLOT == 0) ? g_t1 : g_t2;
    int c = blockIdx.x, s = blockIdx.y, tid = threadIdx.x;
    constexpr int TOT = B * HW, SLICE = TOT / NSLICE;   // 1536

    double ss = 0.0, sq = 0.0;
    for (int j = s * SLICE + tid; j < (s + 1) * SLICE; j += 256) {
        int b = j / HW, i = j - b * HW;
        double v = t[(size_t)(b * C + c) * HW + i];
        ss += v; sq += v * v;
    }
    __shared__ double sh1[256], sh2[256];
    sh1[tid] = ss; sh2[tid] = sq;
    __syncthreads();
    for (int st = 128; st > 0; st >>= 1) {
        if (tid < st) { sh1[tid] += sh1[tid + st]; sh2[tid] += sh2[tid + st]; }
        __syncthreads();
    }
    if (tid == 0) {
        g_bnpart[SLOT][c][s][0] = sh1[0];
        g_bnpart[SLOT][c][s][1] = sh2[0];
    }
}

template<int SLOT>
__global__ void bn_final_k(const float* __restrict__ gam, const float* __restrict__ bet)
{
    int c = blockIdx.x, tid = threadIdx.x;   // 32 threads
    double ss = 0.0, sq = 0.0;
    if (tid < NSLICE) { ss = g_bnpart[SLOT][c][tid][0]; sq = g_bnpart[SLOT][c][tid][1]; }
    #pragma unroll
    for (int off = 16; off > 0; off >>= 1) {
        ss += __shfl_down_sync(0xffffffffu, ss, off);
        sq += __shfl_down_sync(0xffffffffu, sq, off);
    }
    if (tid == 0) {
        double n = (double)B * HW;
        double mu = ss / n;
        double var = sq / n - mu * mu;
        float scale = gam[c] * rsqrtf((float)var + 1e-5f);
        g_bnscale[SLOT][c] = scale;
        g_bnshift[SLOT][c] = bet[c] - (float)mu * scale;
    }
}

// ---------------- transpose x: [B,C,HW] -> [B,HW,C] -------------------------
__global__ void transpose_k(const float* __restrict__ x)
{
    __shared__ float t[32][33];
    int b = blockIdx.z;
    int hw0 = blockIdx.x * 32, c0 = blockIdx.y * 32;
    int tx = threadIdx.x, ty = threadIdx.y;
    #pragma unroll
    for (int j = 0; j < 32; j += 8)
        t[ty + j][tx] = x[(size_t)(b * C + c0 + ty + j) * HW + hw0 + tx];
    __syncthreads();
    #pragma unroll
    for (int j = 0; j < 32; j += 8)
        g_xt[(size_t)(b * HW + hw0 + ty + j) * C + c0 + tx] = t[tx][ty + j];
}

// ---------------- copy x into out channels [0,64) ---------------------------
__global__ void copy_x_k(const float* __restrict__ x, float* __restrict__ out)
{
    int i = blockIdx.x * blockDim.x + threadIdx.x;
    if (i < B * C * HW) {
        int b = i / (C * HW);
        int rem = i - b * (C * HW);
        out[(size_t)b * (2 * C * HW) + rem] = x[i];
    }
}

// ---------------- horizontal pass: sq-dist + running 10-window sum ----------
// block = (h, b, dy-group); 96 threads = 8 dx-groups x 12 w-chunks (8 px each).
// Per dy: write all 21 dx s-rows into zero-padded srow, one sync, then each
// thread slides a 10-wide running sum over its chunk (~3 LDS/px vs 10).
__global__ void __launch_bounds__(96) hs_k()
{
    int h = blockIdx.x, b = blockIdx.y, grp = blockIdx.z;
    int tid = threadIdx.x;
    const int dy0 = grp ? 11 : 0;
    const int ndy = grp ? 10 : 11;
    const int par = tid / 12;        // dx group 0..7
    const int wc  = tid % 12;        // w chunk 0..11
    const int w0  = wc * 8;

    __shared__ __align__(16) float rows[11][96][8];  // 33.8 KB
    __shared__ __align__(16) float cen[96][8];       // 3 KB
    __shared__ float cnorm[96];
    __shared__ float srow[WS][112];                  // 9.4 KB, pads stay 0

    // zero srow (one time; pads [0,4) and [100,112) never overwritten)
    for (int i = tid; i < WS * 112; i += 96) (&srow[0][0])[i] = 0.f;

    for (int i = tid; i < ndy * 96 * 2; i += 96) {
        int rr = i / 192, rem = i % 192, ww = rem >> 1, hf = rem & 1;
        int gh = h + (dy0 + rr) - Rr;
        float4 v = make_float4(0.f, 0.f, 0.f, 0.f);
        if (gh >= 0 && gh < H)
            v = *(const float4*)(g_xe + ((size_t)(b * H + gh) * W + ww) * E + hf * 4);
        *(float4*)(&rows[rr][ww][0] + hf * 4) = v;
    }
    for (int i = tid; i < 96 * 2; i += 96) {
        int ww = i >> 1, hf = i & 1;
        float4 v = *(const float4*)(g_xe + ((size_t)(b * H + h) * W + ww) * E + hf * 4);
        *(float4*)(&cen[ww][0] + hf * 4) = v;
    }
    __syncthreads();
    {
        float4 a  = *(float4*)&cen[tid][0];
        float4 a2 = *(float4*)&cen[tid][4];
        cnorm[tid] = a.x*a.x + a.y*a.y + a.z*a.z + a.w*a.w
                   + a2.x*a2.x + a2.y*a2.y + a2.z*a2.z + a2.w*a2.w;
    }
    __syncthreads();

    for (int i = 0; i < ndy; i++) {
        int dyi = dy0 + i;
        #pragma unroll
        for (int k = 0; k < 3; k++) {
            int dx = par + 8 * k;
            if (dx < WS) {
                #pragma unroll
                for (int j = 0; j < 8; j++) {
                    int w = w0 + j;
                    int ws = w + dx - Rr;
                    float s;
                    if ((unsigned)ws < (unsigned)W) {
                        float4 a  = *(float4*)&cen[w][0];
                        float4 a2 = *(float4*)&cen[w][4];
                        float4 bb = *(float4*)&rows[i][ws][0];
                        float4 b2 = *(float4*)&rows[i][ws][4];
                        float d0 = a.x - bb.x, d1 = a.y - bb.y, d2 = a.z - bb.z, d3 = a.w - bb.w;
                        float d4 = a2.x - b2.x, d5 = a2.y - b2.y, d6 = a2.z - b2.z, d7 = a2.w - b2.w;
                        s = d0*d0 + d1*d1 + d2*d2 + d3*d3 + d4*d4 + d5*d5 + d6*d6 + d7*d7;
                    } else {
                        s = cnorm[w];
                    }
                    srow[dx][4 + w] = s;
                }
            }
        }
        __syncthreads();
        #pragma unroll
        for (int k = 0; k < 3; k++) {
            int dx = par + 8 * k;
            if (dx < WS) {
                int o = dyi * WS + dx;
                float* dst = g_hs + ((size_t)(o * B + b) * H + h) * W;
                float hsum = 0.f;
                #pragma unroll
                for (int t = 0; t < 10; t++) hsum += srow[dx][w0 + t];
                #pragma unroll
                for (int j = 0; j < 8; j++) {
                    int w = w0 + j;
                    dst[w] = hsum;
                    hsum += srow[dx][4 + w + 6] - srow[dx][4 + w - 4];
                }
            }
        }
        __syncthreads();
    }
}

// ---------------- vertical pass: 10-tall running window + validity mask -----
__global__ void __launch_bounds__(96) vert_k()
{
    int o = blockIdx.x, b = blockIdx.y, w = threadIdx.x;
    int dy = o / WS - Rr, dx = o % WS - Rr;
    bool colv = (unsigned)(w + dx) < (unsigned)W;
    bool notc = (dy != 0) || (dx != 0);
    const float* base = g_hs + (size_t)(o * B + b) * HW;
    float* dst = g_D + (size_t)(o * B + b) * HW;

    float rsum = 0.f;
    #pragma unroll
    for (int r = 0; r < 6; r++) rsum += base[r * W + w];

    for (int hh = 0; hh < H; hh++) {
        int vh = hh + dy;
        bool valid = colv && notc && (vh >= 0) && (vh < H);
        dst[hh * W + w] = valid ? rsum : BIGV;
        if (hh + 6 < H)  rsum += base[(hh + 6) * W + w];
        if (hh - 4 >= 0) rsum -= base[(hh - 4) * W + w];
    }
}

// ---------------- top-7 + softmax + gather-aggregate ------------------------
__global__ void __launch_bounds__(96) topk_agg_k(float* __restrict__ out)
{
    int h = blockIdx.x, b = blockIdx.y;
    int w = threadIdx.x;

    float vals[KNN];
    int   idxs[KNN];
    #pragma unroll
    for (int k = 0; k < KNN; k++) { vals[k] = 3.4e38f; idxs[k] = 0; }

    const float* dp = g_D + ((size_t)b * H + h) * W + w;
    const size_t ostride = (size_t)B * HW;

    for (int o = 0; o < NOFF; o++) {
        float d = dp[(size_t)o * ostride];
        if (d < vals[KNN - 1]) {          // strict: keeps lowest-index on ties
            vals[KNN - 1] = d; idxs[KNN - 1] = o;
            #pragma unroll
            for (int j = KNN - 1; j >= 1; j--) {
                if (vals[j] < vals[j - 1]) {
                    float tv = vals[j]; vals[j] = vals[j - 1]; vals[j - 1] = tv;
                    int ti = idxs[j]; idxs[j] = idxs[j - 1]; idxs[j - 1] = ti;
                }
            }
        }
    }

    float e[KNN]; float sum = 0.f;
    #pragma unroll
    for (int k = 0; k < KNN; k++) { e[k] = expf(vals[0] - vals[k]); sum += e[k]; }
    float inv = 1.f / sum;

    float acc[C];
    #pragma unroll
    for (int c = 0; c < C; c++) acc[c] = 0.f;

    for (int k = 0; k < KNN; k++) {
        int o = idxs[k];
        float wt = e[k] * inv;
        int y  = h + o / WS - Rr;
        int xx = w + o % WS - Rr;
        const float4* nb = (const float4*)(g_xt + ((size_t)(b * H + y) * W + xx) * C);
        #pragma unroll
        for (int q = 0; q < C / 4; q++) {
            float4 v = nb[q];
            acc[4 * q + 0] += wt * v.x;
            acc[4 * q + 1] += wt * v.y;
            acc[4 * q + 2] += wt * v.z;
            acc[4 * q + 3] += wt * v.w;
        }
    }

    float* op = out + ((size_t)(b * 2 * C + C)) * HW + h * W + w;
    #pragma unroll
    for (int c = 0; c < C; c++) op[(size_t)c * HW] = acc[c];
}

// ---------------- launch -----------------------------------------------------
extern "C" void kernel_launch(void* const* d_in, const int* in_sizes, int n_in,
                              void* d_out, int out_size)
{
    const float* x  = (const float*)d_in[0];
    // d_in[1] = flows (unused)
    const float* w1 = (const float*)d_in[2];
    const float* g1 = (const float*)d_in[3];
    const float* b1 = (const float*)d_in[4];
    const float* w2 = (const float*)d_in[5];
    const float* g2 = (const float*)d_in[6];
    const float* b2 = (const float*)d_in[7];
    const float* w3 = (const float*)d_in[8];
    const float* b3 = (const float*)d_in[9];
    float* out = (float*)d_out;

    dim3 cblk(16, 4);
    conv3x3_k<0><<<dim3(W / 16, H / 16, B * 8), cblk>>>(x, w1);
    bn_partial_k<0><<<dim3(C, NSLICE), 256>>>();
    bn_final_k<0><<<C, 32>>>(g1, b1);
    conv3x3_k<1><<<dim3(W / 16, H / 16, B * 8), cblk>>>(x, w2);
    bn_partial_k<1><<<dim3(C, NSLICE), 256>>>();
    bn_final_k<1><<<C, 32>>>(g2, b2);
    conv3e_k<<<dim3(W / 16, H / 4, B), cblk>>>(w3, b3);

    transpose_k<<<dim3(HW / 32, C / 32, B), dim3(32, 8)>>>(x);
    copy_x_k<<<(B * C * HW + 255) / 256, 256>>>(x, out);

    hs_k<<<dim3(H, B, 2), 96>>>();
    vert_k<<<dim3(NOFF, B), 96>>>();
    topk_agg_k<<<dim3(H, B), 96>>>(out);
}

// round 14
// speedup vs baseline: 1.3585x; 1.3585x over previous
#include <cuda_runtime.h>
#include <cuda_bf16.h>
#include <cstdint>

// Problem constants
constexpr int B = 4, C = 64, H = 96, W = 96, F = 64, E = 8;
constexpr int WS = 21, PS = 10, KNN = 7, Rr = 10, NOFF = WS * WS; // 441
constexpr int HW = H * W;
constexpr float BIGV = 1e10f;
constexpr int NSLICE = 24;               // BN reduction slices

// ---------------- scratch (device globals; no allocation allowed) ----------
__device__ float g_t1[B * C * HW];            // conv1 raw output
__device__ float g_t2[B * C * HW];            // conv2 raw output
__device__ float g_xe[B * HW * E];            // embedding, [B,H,W,E]
__device__ float g_xt[B * HW * C];            // x transposed, [B,H,W,C]
__device__ float g_hs[NOFF * B * HW];         // horizontal 10-window sums
__device__ float g_D [NOFF * B * HW];         // full 10x10 distances (masked)
__device__ float g_bnscale[2][C];
__device__ float g_bnshift[2][C];
__device__ double g_bnpart[2][C][NSLICE][2];  // partial (sum, sumsq)

// ---------------- conv 3x3 SAME (stages 0/1: 64->64) ------------------------
// block (16,4) = 64 thr: 16x16 tile, each thread 1 col x 4 rows, 8 co.
// Halo slots precomputed, weights padded for LDS.128, double-buffered tile.
template<int STAGE>
__global__ void __launch_bounds__(64) conv3x3_k(const float* __restrict__ xin,
                                                const float* __restrict__ wgt)
{
    constexpr int CIN = 64;
    const float* in = (STAGE == 0) ? xin : g_t1;
    float* outp     = (STAGE == 0) ? g_t1 : g_t2;

    const int tx = threadIdx.x, ty = threadIdx.y;
    const int tid = ty * 16 + tx;
    const int gx0 = blockIdx.x * 16, gy0 = blockIdx.y * 16;
    const int b   = blockIdx.z >> 3;
    const int co0 = (blockIdx.z & 7) * 8;

    __shared__ __align__(16) float wsm[CIN][8][12];  // padded: 2xLDS.128+LDS.32
    __shared__ float tile[2][344];                   // 18x19 + dump slot 343

    for (int i = tid; i < CIN * 8 * 9; i += 64) {
        int cin = i / 72, rem = i % 72, co = rem / 9, k = rem % 9;
        wsm[cin][co][k] = wgt[((co0 + co) * CIN + cin) * 9 + k];
    }

    int  sm_idx[6];
    int  goff[6];
    bool inb[6];
    #pragma unroll
    for (int s = 0; s < 6; s++) {
        int i = tid + s * 64;
        if (i < 324) {
            int r = i / 18, c = i % 18;
            int gy = gy0 + r - 1, gx = gx0 + c - 1;
            bool ok = (gy >= 0) && (gy < H) && (gx >= 0) && (gx < W);
            sm_idx[s] = r * 19 + c;
            goff[s]   = ok ? (gy * W + gx) : 0;
            inb[s]    = ok;
        } else {
            sm_idx[s] = 343; goff[s] = 0; inb[s] = false;
        }
    }

    const float* ipb = in + (size_t)b * CIN * HW;

    float acc[8][4];
    #pragma unroll
    for (int co = 0; co < 8; co++)
        #pragma unroll
        for (int p = 0; p < 4; p++) acc[co][p] = 0.f;

    {
        float sc = 1.f, sh = 0.f;
        if (STAGE == 1) { sc = g_bnscale[0][0]; sh = g_bnshift[0][0]; }
        #pragma unroll
        for (int s = 0; s < 6; s++) {
            float v = 0.f;
            if (inb[s]) {
                v = ipb[goff[s]];
                if (STAGE == 1) v = fmaxf(v * sc + sh, 0.f);
            }
            tile[0][sm_idx[s]] = v;
        }
    }
    __syncthreads();

    for (int cin = 0; cin < CIN; cin++) {
        const int cur = cin & 1;

        if (cin + 1 < CIN) {
            float sc = 1.f, sh = 0.f;
            if (STAGE == 1) { sc = g_bnscale[0][cin + 1]; sh = g_bnshift[0][cin + 1]; }
            const float* ip = ipb + (size_t)(cin + 1) * HW;
            #pragma unroll
            for (int s = 0; s < 6; s++) {
                float v = 0.f;
                if (inb[s]) {
                    v = ip[goff[s]];
                    if (STAGE == 1) v = fmaxf(v * sc + sh, 0.f);
                }
                tile[cur ^ 1][sm_idx[s]] = v;
            }
        }

        const float* tb = tile[cur];
        float tin[6][3];
        #pragma unroll
        for (int rr = 0; rr < 6; rr++)
            #pragma unroll
            for (int cc = 0; cc < 3; cc++)
                tin[rr][cc] = tb[(ty * 4 + rr) * 19 + tx + cc];

        #pragma unroll
        for (int co = 0; co < 8; co++) {
            const float4 w0 = *(const float4*)&wsm[cin][co][0];
            const float4 w1 = *(const float4*)&wsm[cin][co][4];
            const float  w8 = wsm[cin][co][8];
            #pragma unroll
            for (int p = 0; p < 4; p++) {
                float a = acc[co][p];
                a += w0.x * tin[p    ][0];
                a += w0.y * tin[p    ][1];
                a += w0.z * tin[p    ][2];
                a += w0.w * tin[p + 1][0];
                a += w1.x * tin[p + 1][1];
                a += w1.y * tin[p + 1][2];
                a += w1.z * tin[p + 2][0];
                a += w1.w * tin[p + 2][1];
                a += w8   * tin[p + 2][2];
                acc[co][p] = a;
            }
        }
        __syncthreads();
    }

    #pragma unroll
    for (int co = 0; co < 8; co++) {
        #pragma unroll
        for (int p = 0; p < 4; p++) {
            int gy = gy0 + ty * 4 + p, gx = gx0 + tx;
            outp[((size_t)(b * CIN + co0 + co) * H + gy) * W + gx] = acc[co][p];
        }
    }
}

// ---------------- conv3: 64->8 embedding, tile 16x4 (occupancy fix) ---------
__global__ void __launch_bounds__(64) conv3e_k(const float* __restrict__ wgt,
                                               const float* __restrict__ bias)
{
    constexpr int CIN = 64;
    const int tx = threadIdx.x, ty = threadIdx.y;      // (16,4)
    const int tid = ty * 16 + tx;
    const int gx0 = blockIdx.x * 16, gy0 = blockIdx.y * 4;
    const int b   = blockIdx.z;

    __shared__ __align__(16) float wsm[CIN][8][12];
    __shared__ float tile[2][120];                     // 6x19 + dump slot 119

    for (int i = tid; i < CIN * 8 * 9; i += 64) {
        int cin = i / 72, rem = i % 72, co = rem / 9, k = rem % 9;
        wsm[cin][co][k] = wgt[(co * CIN + cin) * 9 + k];
    }

    // halo: 6 rows x 18 cols = 108 slots -> 2 per thread
    int  sm_idx[2];
    int  goff[2];
    bool inb[2];
    #pragma unroll
    for (int s = 0; s < 2; s++) {
        int i = tid + s * 64;
        if (i < 108) {
            int r = i / 18, c = i % 18;
            int gy = gy0 + r - 1, gx = gx0 + c - 1;
            bool ok = (gy >= 0) && (gy < H) && (gx >= 0) && (gx < W);
            sm_idx[s] = r * 19 + c;
            goff[s]   = ok ? (gy * W + gx) : 0;
            inb[s]    = ok;
        } else {
            sm_idx[s] = 119; goff[s] = 0; inb[s] = false;
        }
    }

    const float* ipb = g_t2 + (size_t)b * CIN * HW;

    float acc[8];
    #pragma unroll
    for (int co = 0; co < 8; co++) acc[co] = 0.f;

    {
        float sc = g_bnscale[1][0], sh = g_bnshift[1][0];
        #pragma unroll
        for (int s = 0; s < 2; s++) {
            float v = 0.f;
            if (inb[s]) v = fmaxf(ipb[goff[s]] * sc + sh, 0.f);
            tile[0][sm_idx[s]] = v;
        }
    }
    __syncthreads();

    for (int cin = 0; cin < CIN; cin++) {
        const int cur = cin & 1;
        if (cin + 1 < CIN) {
            float sc = g_bnscale[1][cin + 1], sh = g_bnshift[1][cin + 1];
            const float* ip = ipb + (size_t)(cin + 1) * HW;
            #pragma unroll
            for (int s = 0; s < 2; s++) {
                float v = 0.f;
                if (inb[s]) v = fmaxf(ip[goff[s]] * sc + sh, 0.f);
                tile[cur ^ 1][sm_idx[s]] = v;
            }
        }

        const float* tb = tile[cur];
        float tin[3][3];
        #pragma unroll
        for (int rr = 0; rr < 3; rr++)
            #pragma unroll
            for (int cc = 0; cc < 3; cc++)
                tin[rr][cc] = tb[(ty + rr) * 19 + tx + cc];

        #pragma unroll
        for (int co = 0; co < 8; co++) {
            const float4 w0 = *(const float4*)&wsm[cin][co][0];
            const float4 w1 = *(const float4*)&wsm[cin][co][4];
            const float  w8 = wsm[cin][co][8];
            float a = acc[co];
            a += w0.x * tin[0][0];
            a += w0.y * tin[0][1];
            a += w0.z * tin[0][2];
            a += w0.w * tin[1][0];
            a += w1.x * tin[1][1];
            a += w1.y * tin[1][2];
            a += w1.z * tin[2][0];
            a += w1.w * tin[2][1];
            a += w8   * tin[2][2];
            acc[co] = a;
        }
        __syncthreads();
    }

    const int gy = gy0 + ty, gx = gx0 + tx;
    float4 o0 = make_float4(acc[0] + bias[0], acc[1] + bias[1],
                            acc[2] + bias[2], acc[3] + bias[3]);
    float4 o1 = make_float4(acc[4] + bias[4], acc[5] + bias[5],
                            acc[6] + bias[6], acc[7] + bias[7]);
    float* dst = g_xe + ((size_t)(b * H + gy) * W + gx) * E;
    *(float4*)dst       = o0;
    *(float4*)(dst + 4) = o1;
}

// ---------------- BN statistics: two-stage deterministic --------------------
template<int SLOT>
__global__ void bn_partial_k()
{
    const float* t = (SLOT == 0) ? g_t1 : g_t2;
    int c = blockIdx.x, s = blockIdx.y, tid = threadIdx.x;
    constexpr int TOT = B * HW, SLICE = TOT / NSLICE;   // 1536

    double ss = 0.0, sq = 0.0;
    for (int j = s * SLICE + tid; j < (s + 1) * SLICE; j += 256) {
        int b = j / HW, i = j - b * HW;
        double v = t[(size_t)(b * C + c) * HW + i];
        ss += v; sq += v * v;
    }
    __shared__ double sh1[256], sh2[256];
    sh1[tid] = ss; sh2[tid] = sq;
    __syncthreads();
    for (int st = 128; st > 0; st >>= 1) {
        if (tid < st) { sh1[tid] += sh1[tid + st]; sh2[tid] += sh2[tid + st]; }
        __syncthreads();
    }
    if (tid == 0) {
        g_bnpart[SLOT][c][s][0] = sh1[0];
        g_bnpart[SLOT][c][s][1] = sh2[0];
    }
}

template<int SLOT>
__global__ void bn_final_k(const float* __restrict__ gam, const float* __restrict__ bet)
{
    int c = blockIdx.x, tid = threadIdx.x;   // 32 threads
    double ss = 0.0, sq = 0.0;
    if (tid < NSLICE) { ss = g_bnpart[SLOT][c][tid][0]; sq = g_bnpart[SLOT][c][tid][1]; }
    #pragma unroll
    for (int off = 16; off > 0; off >>= 1) {
        ss += __shfl_down_sync(0xffffffffu, ss, off);
        sq += __shfl_down_sync(0xffffffffu, sq, off);
    }
    if (tid == 0) {
        double n = (double)B * HW;
        double mu = ss / n;
        double var = sq / n - mu * mu;
        float scale = gam[c] * rsqrtf((float)var + 1e-5f);
        g_bnscale[SLOT][c] = scale;
        g_bnshift[SLOT][c] = bet[c] - (float)mu * scale;
    }
}

// ---------------- transpose x: [B,C,HW] -> [B,HW,C] -------------------------
__global__ void transpose_k(const float* __restrict__ x)
{
    __shared__ float t[32][33];
    int b = blockIdx.z;
    int hw0 = blockIdx.x * 32, c0 = blockIdx.y * 32;
    int tx = threadIdx.x, ty = threadIdx.y;
    #pragma unroll
    for (int j = 0; j < 32; j += 8)
        t[ty + j][tx] = x[(size_t)(b * C + c0 + ty + j) * HW + hw0 + tx];
    __syncthreads();
    #pragma unroll
    for (int j = 0; j < 32; j += 8)
        g_xt[(size_t)(b * HW + hw0 + ty + j) * C + c0 + tx] = t[tx][ty + j];
}

// ---------------- copy x into out channels [0,64) ---------------------------
__global__ void copy_x_k(const float* __restrict__ x, float* __restrict__ out)
{
    int i = blockIdx.x * blockDim.x + threadIdx.x;
    if (i < B * C * HW) {
        int b = i / (C * HW);
        int rem = i - b * (C * HW);
        out[(size_t)b * (2 * C * HW) + rem] = x[i];
    }
}

// ---------------- horizontal pass: sq-dist + 10-wide window sum -------------
// block = (h, b, dy-group); 96 threads (w). Zero-padded srow removes bounds
// predicates in the 10-tap sum (pads == 0 == SAME zero padding).
__global__ void __launch_bounds__(96) hs_k()
{
    int h = blockIdx.x, b = blockIdx.y, grp = blockIdx.z;
    int w = threadIdx.x;
    const int dy0 = grp ? 11 : 0;
    const int ndy = grp ? 10 : 11;

    __shared__ __align__(16) float rows[11][96][8];
    __shared__ float srow[WS][112];                // [dx][4 pad | 96 | 12 pad]

    for (int i = w; i < WS * 112; i += 96) (&srow[0][0])[i] = 0.f;

    for (int i = w; i < ndy * 96 * 2; i += 96) {
        int rr = i / 192, rem = i % 192, ww = rem >> 1, hf = rem & 1;
        int gh = h + (dy0 + rr) - Rr;
        float4 v = make_float4(0.f, 0.f, 0.f, 0.f);
        if (gh >= 0 && gh < H)
            v = *(const float4*)(g_xe + ((size_t)(b * H + gh) * W + ww) * E + hf * 4);
        *(float4*)(&rows[rr][ww][0] + hf * 4) = v;
    }

    float4 ca = *(const float4*)(g_xe + ((size_t)(b * H + h) * W + w) * E);
    float4 cb = *(const float4*)(g_xe + ((size_t)(b * H + h) * W + w) * E + 4);
    float cn = ca.x*ca.x + ca.y*ca.y + ca.z*ca.z + ca.w*ca.w
             + cb.x*cb.x + cb.y*cb.y + cb.z*cb.z + cb.w*cb.w;
    __syncthreads();

    for (int i = 0; i < ndy; i++) {
        int dyi = dy0 + i;
        #pragma unroll 3
        for (int dx = 0; dx < WS; dx++) {
            int ws = w + dx - Rr;
            float s;
            if ((unsigned)ws < (unsigned)W) {
                float4 a  = *(float4*)&rows[i][ws][0];
                float4 a2 = *(float4*)&rows[i][ws][4];
                float d0 = ca.x - a.x,  d1 = ca.y - a.y,  d2 = ca.z - a.z,  d3 = ca.w - a.w;
                float d4 = cb.x - a2.x, d5 = cb.y - a2.y, d6 = cb.z - a2.z, d7 = cb.w - a2.w;
                s = d0*d0 + d1*d1 + d2*d2 + d3*d3 + d4*d4 + d5*d5 + d6*d6 + d7*d7;
            } else {
                s = cn;
            }
            srow[dx][4 + w] = s;
        }
        __syncthreads();
        #pragma unroll 3
        for (int dx = 0; dx < WS; dx++) {
            float acc = 0.f;
            #pragma unroll
            for (int dw = 0; dw < 10; dw++) acc += srow[dx][w + dw];  // pads = 0
            int o = dyi * WS + dx;
            g_hs[((size_t)(o * B + b) * H + h) * W + w] = acc;
        }
        __syncthreads();
    }
}

// ---------------- vertical pass: 10-tall running window + validity mask -----
__global__ void __launch_bounds__(96) vert_k()
{
    int o = blockIdx.x, b = blockIdx.y, w = threadIdx.x;
    int dy = o / WS - Rr, dx = o % WS - Rr;
    bool colv = (unsigned)(w + dx) < (unsigned)W;
    bool notc = (dy != 0) || (dx != 0);
    const float* base = g_hs + (size_t)(o * B + b) * HW;
    float* dst = g_D + (size_t)(o * B + b) * HW;

    float rsum = 0.f;
    #pragma unroll
    for (int r = 0; r < 6; r++) rsum += base[r * W + w];

    for (int hh = 0; hh < H; hh++) {
        int vh = hh + dy;
        bool valid = colv && notc && (vh >= 0) && (vh < H);
        dst[hh * W + w] = valid ? rsum : BIGV;
        if (hh + 6 < H)  rsum += base[(hh + 6) * W + w];
        if (hh - 4 >= 0) rsum -= base[(hh - 4) * W + w];
    }
}

// ---------------- top-7 + softmax + gather-aggregate ------------------------
__global__ void __launch_bounds__(96) topk_agg_k(float* __restrict__ out)
{
    int h = blockIdx.x, b = blockIdx.y;
    int w = threadIdx.x;

    float vals[KNN];
    int   idxs[KNN];
    #pragma unroll
    for (int k = 0; k < KNN; k++) { vals[k] = 3.4e38f; idxs[k] = 0; }

    const float* dp = g_D + ((size_t)b * H + h) * W + w;
    const size_t ostride = (size_t)B * HW;

    for (int o = 0; o < NOFF; o++) {
        float d = dp[(size_t)o * ostride];
        if (d < vals[KNN - 1]) {          // strict: keeps lowest-index on ties
            vals[KNN - 1] = d; idxs[KNN - 1] = o;
            #pragma unroll
            for (int j = KNN - 1; j >= 1; j--) {
                if (vals[j] < vals[j - 1]) {
                    float tv = vals[j]; vals[j] = vals[j - 1]; vals[j - 1] = tv;
                    int ti = idxs[j]; idxs[j] = idxs[j - 1]; idxs[j - 1] = ti;
                }
            }
        }
    }

    float e[KNN]; float sum = 0.f;
    #pragma unroll
    for (int k = 0; k < KNN; k++) { e[k] = expf(vals[0] - vals[k]); sum += e[k]; }
    float inv = 1.f / sum;

    float acc[C];
    #pragma unroll
    for (int c = 0; c < C; c++) acc[c] = 0.f;

    for (int k = 0; k < KNN; k++) {
        int o = idxs[k];
        float wt = e[k] * inv;
        int y  = h + o / WS - Rr;
        int xx = w + o % WS - Rr;
        const float4* nb = (const float4*)(g_xt + ((size_t)(b * H + y) * W + xx) * C);
        #pragma unroll
        for (int q = 0; q < C / 4; q++) {
            float4 v = nb[q];
            acc[4 * q + 0] += wt * v.x;
            acc[4 * q + 1] += wt * v.y;
            acc[4 * q + 2] += wt * v.z;
            acc[4 * q + 3] += wt * v.w;
        }
    }

    float* op = out + ((size_t)(b * 2 * C + C)) * HW + h * W + w;
    #pragma unroll
    for (int c = 0; c < C; c++) op[(size_t)c * HW] = acc[c];
}

// ---------------- launch -----------------------------------------------------
extern "C" void kernel_launch(void* const* d_in, const int* in_sizes, int n_in,
                              void* d_out, int out_size)
{
    const float* x  = (const float*)d_in[0];
    // d_in[1] = flows (unused)
    const float* w1 = (const float*)d_in[2];
    const float* g1 = (const float*)d_in[3];
    const float* b1 = (const float*)d_in[4];
    const float* w2 = (const float*)d_in[5];
    const float* g2 = (const float*)d_in[6];
    const float* b2 = (const float*)d_in[7];
    const float* w3 = (const float*)d_in[8];
    const float* b3 = (const float*)d_in[9];
    float* out = (float*)d_out;

    dim3 cblk(16, 4);
    conv3x3_k<0><<<dim3(W / 16, H / 16, B * 8), cblk>>>(x, w1);
    bn_partial_k<0><<<dim3(C, NSLICE), 256>>>();
    bn_final_k<0><<<C, 32>>>(g1, b1);
    conv3x3_k<1><<<dim3(W / 16, H / 16, B * 8), cblk>>>(x, w2);
    bn_partial_k<1><<<dim3(C, NSLICE), 256>>>();
    bn_final_k<1><<<C, 32>>>(g2, b2);
    conv3e_k<<<dim3(W / 16, H / 4, B), cblk>>>(w3, b3);

    transpose_k<<<dim3(HW / 32, C / 32, B), dim3(32, 8)>>>(x);
    copy_x_k<<<(B * C * HW + 255) / 256, 256>>>(x, out);

    hs_k<<<dim3(H, B, 2), 96>>>();
    vert_k<<<dim3(NOFF, B), 96>>>();
    topk_agg_k<<<dim3(H, B), 96>>>(out);
}